// round 16
// baseline (speedup 1.0000x reference)
#include <cuda_runtime.h>
#include <cuda_fp16.h>
#include <math.h>
#include <stdint.h>

#define ROWS 64
#define NT   256
#define KQ   512
#define KC   768
#define HID  128
#define DIMO 512
#define SCALE 0.17677669529663687f
#define SQRTD 22.627416997969522f

#define SQH 136
#define SAH 72
#define SBH 72
#define AG    9216               // per-group single A buffer (64*72*2)
#define ABUFB (ROWS * SAH * 2)   // 9216 (phase-1 view: 2-stage shared)
#define BBUFB (128 * SBH * 2)    // 18432

#define O_QH 0
#define O_A  17408
#define O_B1 35840
#define O_B2 72704
#define O_S  109568
#define O_SS 110592
#define SMEM_BYTES 110848

__device__ __half g_wh[327680];

__device__ __forceinline__ void mma16(float* c, const uint32_t* a, uint32_t b0, uint32_t b1) {
    asm volatile(
        "mma.sync.aligned.m16n8k16.row.col.f32.f16.f16.f32 "
        "{%0,%1,%2,%3},{%4,%5,%6,%7},{%8,%9},{%0,%1,%2,%3};"
        : "+f"(c[0]), "+f"(c[1]), "+f"(c[2]), "+f"(c[3])
        : "r"(a[0]), "r"(a[1]), "r"(a[2]), "r"(a[3]), "r"(b0), "r"(b1));
}
__device__ __forceinline__ void ldsm4(uint32_t* r, uint32_t a) {
    asm volatile("ldmatrix.sync.aligned.m8n8.x4.shared.b16 {%0,%1,%2,%3}, [%4];"
                 : "=r"(r[0]), "=r"(r[1]), "=r"(r[2]), "=r"(r[3]) : "r"(a));
}
__device__ __forceinline__ uint32_t s2u(const void* p) {
    return (uint32_t)__cvta_generic_to_shared(p);
}
__device__ __forceinline__ void cpa16(uint32_t s, const void* g) {
    asm volatile("cp.async.cg.shared.global [%0], [%1], 16;" :: "r"(s), "l"(g));
}
#define CPA_COMMIT() asm volatile("cp.async.commit_group;" ::: "memory")
#define CPA_WAIT0()  asm volatile("cp.async.wait_group 0;" ::: "memory")
#define BARG(id)     asm volatile("bar.sync %0, 128;" :: "r"(id) : "memory")

__device__ __forceinline__ uint2 f4toh4(float4 v) {
    __half2 h01 = __floats2half2_rn(v.x, v.y);
    __half2 h23 = __floats2half2_rn(v.z, v.w);
    uint2 r;
    r.x = *(uint32_t*)&h01;
    r.y = *(uint32_t*)&h23;
    return r;
}

__global__ void wtrans(const float* __restrict__ Wq, const float* __restrict__ Wk,
                       const float* __restrict__ Wv, const float* __restrict__ Wo) {
    __shared__ float t[32][33];
    int bid = blockIdx.x;
    const float* src; __half* dst; int K, N, toff;
    if (bid < 64)       { src = Wq; dst = g_wh;          K = 512; N = 128; toff = bid; }
    else if (bid < 160) { src = Wk; dst = g_wh + 65536;  K = 768; N = 128; toff = bid - 64; }
    else if (bid < 256) { src = Wv; dst = g_wh + 163840; K = 768; N = 128; toff = bid - 160; }
    else                { src = Wo; dst = g_wh + 262144; K = 128; N = 512; toff = bid - 256; }
    int ntx = N / 32;
    int tn = (toff % ntx) * 32, tk = (toff / ntx) * 32;
    for (int i = threadIdx.y; i < 32; i += 8)
        t[i][threadIdx.x] = src[(size_t)(tk + i) * N + tn + threadIdx.x];
    __syncthreads();
    for (int i = threadIdx.y; i < 32; i += 8)
        dst[(size_t)(tn + i) * K + tk + threadIdx.x] = __float2half_rn(t[threadIdx.x][i]);
}

__global__ void __launch_bounds__(NT, 2) lca_kernel(
    const float* __restrict__ x, const float* __restrict__ ctx,
    const float* __restrict__ bo, const float* __restrict__ gg,
    float* __restrict__ out) {
    extern __shared__ char smc[];
    __half* sQh = (__half*)(smc + O_QH);
    __half* sAh = (__half*)(smc + O_A);
    float*  sS  = (float*)(smc + O_S);
    float*  sSS = (float*)(smc + O_SS);
    uint32_t sQhu = s2u(smc + O_QH), sAu = s2u(smc + O_A);
    uint32_t sB1u = s2u(smc + O_B1), sB2u = s2u(smc + O_B2);

    int tid = threadIdx.x;
    int warp = tid >> 5, lane = tid & 31;
    int g = lane >> 2, t = lane & 3;
    int wr1 = warp >> 2, wc4 = warp & 3;                              // phase-1 ids
    int grp = warp >> 2, w4 = warp & 3, wr = w4 >> 1, wcg = w4 & 1;   // group ids
    int gt = tid & 127;
    int bar = 1 + grp;
    int rowBase = blockIdx.x * ROWS;
    if (tid < ROWS) sSS[tid] = 0.f;

    uint32_t aOff = (uint32_t)(((lane & 15) * SAH + ((lane >> 4) << 3)) * 2);
    uint32_t bOff = (uint32_t)(((((lane & 7) + ((lane >> 4) << 3)) * SBH) + (((lane >> 3) & 1) << 3)) * 2);
    uint32_t qOff = (uint32_t)(((lane & 15) * SQH + ((lane >> 4) << 3)) * 2);

    // phase-1 fill indices (256 threads, 4 slots)
    int raA[4], kaA[4], rbB[4], kbB[4];
    uint32_t bFill[4];
#pragma unroll
    for (int j = 0; j < 4; j++) {
        int idx = tid + j * NT;
        raA[j] = idx >> 4; kaA[j] = (idx & 15) << 2;
        rbB[j] = idx >> 3; kbB[j] = (idx & 7) << 3;
        bFill[j] = (uint32_t)((rbB[j] * SBH + kbB[j]) * 2);
    }
    // group fill indices (128 threads, 8 slots)
    int raG[8], kaG[8], rnG[8], rkG[8];
    uint32_t bFG[8];
#pragma unroll
    for (int j = 0; j < 8; j++) {
        int idx = gt + j * 128;
        raG[j] = idx >> 4; kaG[j] = (idx & 15) << 2;
        rnG[j] = idx >> 3; rkG[j] = (idx & 7) << 3;
        bFG[j] = (uint32_t)((rnG[j] * SBH + rkG[j]) * 2);
    }

    float acc[16][4];
    const __half* WqT = g_wh;
    const __half* WkT = g_wh + 65536;
    const __half* WvT = g_wh + 163840;
    const __half* WoT = g_wh + 262144;

    // ================= Phase 1: q = x @ Wq (full CTA, as R15) =================
    {
#pragma unroll
        for (int i = 0; i < 8; i++) { acc[i][0] = acc[i][1] = acc[i][2] = acc[i][3] = 0.f; }
        float4 pa[4];
#pragma unroll
        for (int j = 0; j < 4; j++)
            pa[j] = *(const float4*)(x + (size_t)(rowBase + raA[j]) * KQ + kaA[j]);
#pragma unroll
        for (int j = 0; j < 4; j++)
            cpa16(sB1u + bFill[j], WqT + (size_t)rbB[j] * KQ + kbB[j]);
        CPA_COMMIT();
        uint32_t aB = (uint32_t)(wr1 * 32 * SAH * 2) + aOff;
        uint32_t bB = (uint32_t)(wc4 * 32 * SBH * 2) + bOff;
#pragma unroll 1
        for (int i = 0; i < 8; i++) {
            int kc = i * 64, cur = i & 1;
            __half* dA = sAh + cur * (ABUFB / 2);
#pragma unroll
            for (int j = 0; j < 4; j++)
                *(uint2*)(dA + raA[j] * SAH + kaA[j]) = f4toh4(pa[j]);
            if (i + 1 < 8) {
#pragma unroll
                for (int j = 0; j < 4; j++)
                    pa[j] = *(const float4*)(x + (size_t)(rowBase + raA[j]) * KQ + kc + 64 + kaA[j]);
            }
            CPA_WAIT0();
            __syncthreads();
            if (i + 1 < 8) {
#pragma unroll
                for (int j = 0; j < 4; j++)
                    cpa16(sB1u + (cur ^ 1) * BBUFB + bFill[j],
                          WqT + (size_t)rbB[j] * KQ + kc + 64 + kbB[j]);
                CPA_COMMIT();
            }
            uint32_t cA = sAu + cur * ABUFB + aB;
            uint32_t cB = sB1u + cur * BBUFB + bB;
#pragma unroll
            for (int s = 0; s < 4; s++) {
                uint32_t a0[4], a1[4], b[2][4];
                ldsm4(a0, cA + s * 32);
                ldsm4(a1, cA + 16 * SAH * 2 + s * 32);
#pragma unroll
                for (int q = 0; q < 2; q++) ldsm4(b[q], cB + q * (16 * SBH * 2) + s * 32);
#pragma unroll
                for (int q = 0; q < 2; q++) {
                    mma16(acc[2 * q],     a0, b[q][0], b[q][1]);
                    mma16(acc[2 * q + 1], a0, b[q][2], b[q][3]);
                    mma16(acc[4 + 2 * q],     a1, b[q][0], b[q][1]);
                    mma16(acc[4 + 2 * q + 1], a1, b[q][2], b[q][3]);
                }
            }
        }
        // in-warp softmax -> q fp16 to sQh
#pragma unroll
        for (int mt = 0; mt < 2; mt++)
#pragma unroll
            for (int rh = 0; rh < 2; rh++) {
                float v[8];
#pragma unroll
                for (int nt = 0; nt < 4; nt++) {
                    v[2 * nt]     = acc[mt * 4 + nt][rh * 2];
                    v[2 * nt + 1] = acc[mt * 4 + nt][rh * 2 + 1];
                }
                float m = v[0];
#pragma unroll
                for (int j = 1; j < 8; j++) m = fmaxf(m, v[j]);
                m = fmaxf(m, __shfl_xor_sync(0xffffffffu, m, 1));
                m = fmaxf(m, __shfl_xor_sync(0xffffffffu, m, 2));
                float s = 0.f;
#pragma unroll
                for (int j = 0; j < 8; j++) { v[j] = __expf(v[j] - m); s += v[j]; }
                s += __shfl_xor_sync(0xffffffffu, s, 1);
                s += __shfl_xor_sync(0xffffffffu, s, 2);
                float inv = SCALE / s;
                int r = wr1 * 32 + mt * 16 + rh * 8 + g;
#pragma unroll
                for (int nt = 0; nt < 4; nt++) {
                    int c = wc4 * 32 + nt * 8 + 2 * t;
                    *(__half2*)(sQh + r * SQH + c) =
                        __floats2half2_rn(v[2 * nt] * inv, v[2 * nt + 1] * inv);
                }
            }
        __syncthreads();
    }

    // ==== Phase 2+3: per-group decoupled. grp0: k=ctx@Wk; grp1: v=ctx@Wv ====
    {
#pragma unroll
        for (int i = 0; i < 16; i++) { acc[i][0] = acc[i][1] = acc[i][2] = acc[i][3] = 0.f; }
        const __half* myW = grp ? WvT : WkT;
        uint32_t myBu = grp ? sB2u : sB1u;
        __half* myAh = sAh + grp * (AG / 2);
        uint32_t myAu = sAu + grp * AG;
        float4 pav[8];
#pragma unroll
        for (int j = 0; j < 8; j++)
            pav[j] = *(const float4*)(ctx + (size_t)(rowBase + raG[j]) * KC + kaG[j]);
#pragma unroll
        for (int j = 0; j < 8; j++)
            cpa16(myBu + bFG[j], myW + (size_t)rnG[j] * KC + rkG[j]);
        CPA_COMMIT();
        uint32_t aB = (uint32_t)(wr * 32 * SAH * 2) + aOff;
        uint32_t bB = (uint32_t)(wcg * 64 * SBH * 2) + bOff;
#pragma unroll 1
        for (int i = 0; i < 12; i++) {
            int kc = i * 64, cur = i & 1;
            CPA_WAIT0();
            BARG(bar);
#pragma unroll
            for (int j = 0; j < 8; j++)
                *(uint2*)(myAh + raG[j] * SAH + kaG[j]) = f4toh4(pav[j]);
            if (i + 1 < 12) {
#pragma unroll
                for (int j = 0; j < 8; j++)
                    pav[j] = *(const float4*)(ctx + (size_t)(rowBase + raG[j]) * KC + kc + 64 + kaG[j]);
#pragma unroll
                for (int j = 0; j < 8; j++)
                    cpa16(myBu + (cur ^ 1) * BBUFB + bFG[j],
                          myW + (size_t)rnG[j] * KC + kc + 64 + rkG[j]);
                CPA_COMMIT();
            }
            BARG(bar);
            uint32_t cA = myAu + aB;
            uint32_t cB = myBu + cur * BBUFB + bB;
#pragma unroll
            for (int s = 0; s < 4; s++) {
                uint32_t a0[4], a1[4], b[4][4];
                ldsm4(a0, cA + s * 32);
                ldsm4(a1, cA + 16 * SAH * 2 + s * 32);
#pragma unroll
                for (int q = 0; q < 4; q++) ldsm4(b[q], cB + q * (16 * SBH * 2) + s * 32);
#pragma unroll
                for (int q = 0; q < 4; q++) {
                    mma16(acc[2 * q],     a0, b[q][0], b[q][1]);
                    mma16(acc[2 * q + 1], a0, b[q][2], b[q][3]);
                    mma16(acc[8 + 2 * q],     a1, b[q][0], b[q][1]);
                    mma16(acc[8 + 2 * q + 1], a1, b[q][2], b[q][3]);
                }
            }
        }
        // grp0: s[row][head] = <sigmoid(k), q>
        if (grp == 0) {
            float part[2][2][2] = {};
#pragma unroll
            for (int mt = 0; mt < 2; mt++)
#pragma unroll
                for (int nt = 0; nt < 8; nt++) {
                    int hl = nt >> 2;
                    int r = wr * 32 + mt * 16 + g, c = wcg * 64 + nt * 8 + 2 * t;
#pragma unroll
                    for (int e = 0; e < 4; e++) {
                        int rr = r + (e >> 1) * 8, cc = c + (e & 1);
                        float kv = 1.f / (1.f + __expf(-acc[mt * 8 + nt][e]));
                        part[mt][e >> 1][hl] += kv * __half2float(sQh[rr * SQH + cc]);
                    }
                }
#pragma unroll
            for (int mt = 0; mt < 2; mt++)
#pragma unroll
                for (int rh = 0; rh < 2; rh++)
#pragma unroll
                    for (int hl = 0; hl < 2; hl++) {
                        float v = part[mt][rh][hl];
                        v += __shfl_xor_sync(0xffffffffu, v, 1);
                        v += __shfl_xor_sync(0xffffffffu, v, 2);
                        if (t == 0)
                            sS[(wr * 32 + mt * 16 + rh * 8 + g) * 4 + wcg * 2 + hl] = v;
                    }
        }
        __syncthreads();   // s ready; q no longer needed
        // grp1: out = s*v -> sQh
        if (grp == 1) {
#pragma unroll
            for (int mt = 0; mt < 2; mt++)
#pragma unroll
                for (int nt = 0; nt < 8; nt++) {
                    int hl = nt >> 2;
                    int r = wr * 32 + mt * 16 + g, c = wcg * 64 + nt * 8 + 2 * t;
#pragma unroll
                    for (int rh = 0; rh < 2; rh++) {
                        int rr = r + rh * 8;
                        float s = sS[rr * 4 + wcg * 2 + hl];
                        __half2 h = __floats2half2_rn(s * acc[mt * 8 + nt][rh * 2],
                                                      s * acc[mt * 8 + nt][rh * 2 + 1]);
                        *(__half2*)(sQh + rr * SQH + c) = h;
                    }
                }
        }
        __syncthreads();   // out tile ready for both groups
    }

    // ===== Phase 4: y = out @ Wo + bo; per-group pipelines and barriers =====
    {
        uint32_t sBgu = grp ? sB2u : sB1u;
#pragma unroll
        for (int j = 0; j < 8; j++)
            cpa16(sBgu + bFG[j], WoT + (size_t)(grp * 128 + rnG[j]) * HID + rkG[j]);
        CPA_COMMIT();
        uint32_t bB = (uint32_t)(wcg * 64 * SBH * 2) + bOff;
        uint32_t qB = (uint32_t)(wr * 32 * SQH * 2) + qOff;
#pragma unroll 1
        for (int i = 0; i < 4; i++) {
            int kc = (i & 1) * 64, cur = i & 1;
            int nc = (i >> 1) * 2 + grp;
            if ((i & 1) == 0) {
#pragma unroll
                for (int q = 0; q < 16; q++) { acc[q][0] = acc[q][1] = acc[q][2] = acc[q][3] = 0.f; }
            }
            CPA_WAIT0();
            BARG(bar);
            if (i + 1 < 4) {
                int n = i + 1, nk = (n & 1) * 64, nnc = (n >> 1) * 2 + grp;
#pragma unroll
                for (int j = 0; j < 8; j++)
                    cpa16(sBgu + (cur ^ 1) * BBUFB + bFG[j],
                          WoT + (size_t)(nnc * 128 + rnG[j]) * HID + nk + rkG[j]);
                CPA_COMMIT();
            }
            uint32_t cB = sBgu + cur * BBUFB + bB;
            uint32_t cQ = sQhu + qB + kc * 2;
#pragma unroll
            for (int s = 0; s < 4; s++) {
                uint32_t a0[4], a1[4], b[4][4];
                ldsm4(a0, cQ + s * 32);
                ldsm4(a1, cQ + 16 * SQH * 2 + s * 32);
#pragma unroll
                for (int q = 0; q < 4; q++) ldsm4(b[q], cB + q * (16 * SBH * 2) + s * 32);
#pragma unroll
                for (int q = 0; q < 4; q++) {
                    mma16(acc[2 * q],     a0, b[q][0], b[q][1]);
                    mma16(acc[2 * q + 1], a0, b[q][2], b[q][3]);
                    mma16(acc[8 + 2 * q],     a1, b[q][0], b[q][1]);
                    mma16(acc[8 + 2 * q + 1], a1, b[q][2], b[q][3]);
                }
            }
            if ((i & 1) == 1) {
                float rss[2][2] = {};
#pragma unroll
                for (int mt = 0; mt < 2; mt++)
#pragma unroll
                    for (int nt = 0; nt < 8; nt++) {
                        int r = wr * 32 + mt * 16 + g;
                        int c = nc * 128 + wcg * 64 + nt * 8 + 2 * t;
#pragma unroll
                        for (int e = 0; e < 4; e++) {
                            int rr = r + (e >> 1) * 8, cc = c + (e & 1);
                            float y = acc[mt * 8 + nt][e] + __ldg(bo + cc);
                            out[(size_t)(rowBase + rr) * DIMO + cc] = y;
                            rss[mt][e >> 1] += y * y;
                        }
                    }
#pragma unroll
                for (int mt = 0; mt < 2; mt++)
#pragma unroll
                    for (int rh = 0; rh < 2; rh++) {
                        float v = rss[mt][rh];
                        v += __shfl_xor_sync(0xffffffffu, v, 1);
                        v += __shfl_xor_sync(0xffffffffu, v, 2);
                        if (t == 0) atomicAdd(&sSS[wr * 32 + mt * 16 + rh * 8 + g], v);
                    }
            }
        }
    }
    __syncthreads();

    // ---- Phase 5: RMS-normalize in place ----
#pragma unroll 1
    for (int i4 = tid; i4 < ROWS * DIMO / 4; i4 += NT) {
        int r = i4 >> 7, c4 = (i4 & 127) << 2;
        float* p = out + (size_t)(rowBase + r) * DIMO + c4;
        float4 y = *(float4*)p;
        float sc = rsqrtf(fmaxf(sSS[r], 1e-24f)) * SQRTD;
        float4 gv = *(const float4*)(gg + c4);
        y.x *= sc * gv.x; y.y *= sc * gv.y; y.z *= sc * gv.z; y.w *= sc * gv.w;
        *(float4*)p = y;
    }
}

extern "C" void kernel_launch(void* const* d_in, const int* in_sizes, int n_in,
                              void* d_out, int out_size) {
    const float* x   = (const float*)d_in[0];
    const float* ctx = (const float*)d_in[1];
    const float* Wq  = (const float*)d_in[2];
    const float* Wk  = (const float*)d_in[3];
    const float* Wv  = (const float*)d_in[4];
    const float* Wo  = (const float*)d_in[5];
    const float* bo  = (const float*)d_in[6];
    const float* gg  = (const float*)d_in[7];
    wtrans<<<320, dim3(32, 8)>>>(Wq, Wk, Wv, Wo);
    cudaFuncSetAttribute(lca_kernel, cudaFuncAttributeMaxDynamicSharedMemorySize, SMEM_BYTES);
    lca_kernel<<<1024, NT, SMEM_BYTES>>>(x, ctx, bo, gg, (float*)d_out);
}

// round 17
// speedup vs baseline: 1.1276x; 1.1276x over previous
#include <cuda_runtime.h>
#include <cuda_fp16.h>
#include <math.h>
#include <stdint.h>

#define ROWS 64
#define NT   256
#define KQ   512
#define KC   768
#define HID  128
#define DIMO 512
#define SCALE 0.17677669529663687f
#define SQRTD 22.627416997969522f

#define SQH 136   // fp16 q/out tile stride (halfs)
#define SAH 72    // A tile stride (halfs), K=64 chunk
#define SBH 72    // B tile stride (halfs)
#define ABUFB (ROWS * SAH * 2)   // 9216 B
#define BBUFB (128 * SBH * 2)    // 18432 B

// smem byte offsets (2-stage pipes, K=64 chunks)
#define O_QH 0
#define O_A  17408
#define O_B1 35840
#define O_B2 72704
#define O_S  109568
#define O_SS 110592
#define SMEM_BYTES 110848

// pre-transposed fp16 weights, n-major:
// WqT[128][512] | WkT[128][768] | WvT[128][768] | WoT[512][128]
__device__ __half g_wh[327680];

// NOTE: non-volatile on purpose — pure register op, lets ptxas software-pipeline
// MMAs into LDSM latency shadows across the unrolled s-loop.
__device__ __forceinline__ void mma16(float* c, const uint32_t* a, uint32_t b0, uint32_t b1) {
    asm("mma.sync.aligned.m16n8k16.row.col.f32.f16.f16.f32 "
        "{%0,%1,%2,%3},{%4,%5,%6,%7},{%8,%9},{%0,%1,%2,%3};"
        : "+f"(c[0]), "+f"(c[1]), "+f"(c[2]), "+f"(c[3])
        : "r"(a[0]), "r"(a[1]), "r"(a[2]), "r"(a[3]), "r"(b0), "r"(b1));
}
__device__ __forceinline__ void ldsm4(uint32_t* r, uint32_t a) {
    asm volatile("ldmatrix.sync.aligned.m8n8.x4.shared.b16 {%0,%1,%2,%3}, [%4];"
                 : "=r"(r[0]), "=r"(r[1]), "=r"(r[2]), "=r"(r[3]) : "r"(a));
}
__device__ __forceinline__ uint32_t s2u(const void* p) {
    return (uint32_t)__cvta_generic_to_shared(p);
}
__device__ __forceinline__ void cpa16(uint32_t s, const void* g) {
    asm volatile("cp.async.cg.shared.global [%0], [%1], 16;" :: "r"(s), "l"(g));
}
#define CPA_COMMIT() asm volatile("cp.async.commit_group;" ::: "memory")
#define CPA_WAIT0()  asm volatile("cp.async.wait_group 0;" ::: "memory")

__device__ __forceinline__ uint2 f4toh4(float4 v) {
    __half2 h01 = __floats2half2_rn(v.x, v.y);
    __half2 h23 = __floats2half2_rn(v.z, v.w);
    uint2 r;
    r.x = *(uint32_t*)&h01;
    r.y = *(uint32_t*)&h23;
    return r;
}

// ---------- weight transpose + fp16 pre-pass ----------
__global__ void wtrans(const float* __restrict__ Wq, const float* __restrict__ Wk,
                       const float* __restrict__ Wv, const float* __restrict__ Wo) {
    __shared__ float t[32][33];
    int bid = blockIdx.x;
    const float* src; __half* dst; int K, N, toff;
    if (bid < 64)       { src = Wq; dst = g_wh;          K = 512; N = 128; toff = bid; }
    else if (bid < 160) { src = Wk; dst = g_wh + 65536;  K = 768; N = 128; toff = bid - 64; }
    else if (bid < 256) { src = Wv; dst = g_wh + 163840; K = 768; N = 128; toff = bid - 160; }
    else                { src = Wo; dst = g_wh + 262144; K = 128; N = 512; toff = bid - 256; }
    int ntx = N / 32;
    int tn = (toff % ntx) * 32, tk = (toff / ntx) * 32;
    for (int i = threadIdx.y; i < 32; i += 8)
        t[i][threadIdx.x] = src[(size_t)(tk + i) * N + tn + threadIdx.x];
    __syncthreads();
    for (int i = threadIdx.y; i < 32; i += 8)
        dst[(size_t)(tn + i) * K + tk + threadIdx.x] = __float2half_rn(t[threadIdx.x][i]);
}

__global__ void __launch_bounds__(NT, 2) lca_kernel(
    const float* __restrict__ x, const float* __restrict__ ctx,
    const float* __restrict__ bo, const float* __restrict__ gg,
    float* __restrict__ out) {
    extern __shared__ char smc[];
    __half* sQh = (__half*)(smc + O_QH);
    __half* sAh = (__half*)(smc + O_A);
    float*  sS  = (float*)(smc + O_S);
    float*  sSS = (float*)(smc + O_SS);
    uint32_t sQhu = s2u(smc + O_QH), sAu = s2u(smc + O_A);
    uint32_t sB1u = s2u(smc + O_B1), sB2u = s2u(smc + O_B2);

    int tid = threadIdx.x;
    int warp = tid >> 5, lane = tid & 31;
    int g = lane >> 2, t = lane & 3;
    int wr1 = warp >> 2, wc4 = warp & 3;                              // phase-1 ids
    int grp = warp >> 2, w4 = warp & 3, wr = w4 >> 1, wcg = w4 & 1;   // group ids (ph 2-4)
    int rowBase = blockIdx.x * ROWS;
    if (tid < ROWS) sSS[tid] = 0.f;

    // ldmatrix lane offsets (bytes)
    uint32_t aOff = (uint32_t)(((lane & 15) * SAH + ((lane >> 4) << 3)) * 2);
    uint32_t bOff = (uint32_t)(((((lane & 7) + ((lane >> 4) << 3)) * SBH) + (((lane >> 3) & 1) << 3)) * 2);
    uint32_t qOff = (uint32_t)(((lane & 15) * SQH + ((lane >> 4) << 3)) * 2);

    // fill indices (K=64 chunks)
    int raA[4], kaA[4];   // A: 64 rows x 64 halfs, 4-float slots
#pragma unroll
    for (int j = 0; j < 4; j++) {
        int idx = tid + j * NT;
        raA[j] = idx >> 4; kaA[j] = (idx & 15) << 2;
    }
    int rbB[4], kbB[4];   // B: 128 rows x 64 halfs, 16B slots
    uint32_t bFill[4];
#pragma unroll
    for (int j = 0; j < 4; j++) {
        int idx = tid + j * NT;
        rbB[j] = idx >> 3; kbB[j] = (idx & 7) << 3;
        bFill[j] = (uint32_t)((rbB[j] * SBH + kbB[j]) * 2);
    }

    float acc[16][4];
    const __half* WqT = g_wh;
    const __half* WkT = g_wh + 65536;
    const __half* WvT = g_wh + 163840;
    const __half* WoT = g_wh + 262144;

    // ================= Phase 1: q = x @ Wq (8 warps, 32x32 tiles) =================
    {
#pragma unroll
        for (int i = 0; i < 8; i++) { acc[i][0] = acc[i][1] = acc[i][2] = acc[i][3] = 0.f; }
        float4 pa[4];
#pragma unroll
        for (int j = 0; j < 4; j++)
            pa[j] = *(const float4*)(x + (size_t)(rowBase + raA[j]) * KQ + kaA[j]);
#pragma unroll
        for (int j = 0; j < 4; j++)
            cpa16(sB1u + bFill[j], WqT + (size_t)rbB[j] * KQ + kbB[j]);
        CPA_COMMIT();
        uint32_t aB = (uint32_t)(wr1 * 32 * SAH * 2) + aOff;
        uint32_t bB = (uint32_t)(wc4 * 32 * SBH * 2) + bOff;
#pragma unroll 1
        for (int i = 0; i < 8; i++) {
            int kc = i * 64, cur = i & 1;
            __half* dA = sAh + cur * (ABUFB / 2);
#pragma unroll
            for (int j = 0; j < 4; j++)
                *(uint2*)(dA + raA[j] * SAH + kaA[j]) = f4toh4(pa[j]);
            if (i + 1 < 8) {
#pragma unroll
                for (int j = 0; j < 4; j++)
                    pa[j] = *(const float4*)(x + (size_t)(rowBase + raA[j]) * KQ + kc + 64 + kaA[j]);
            }
            CPA_WAIT0();
            __syncthreads();
            if (i + 1 < 8) {
#pragma unroll
                for (int j = 0; j < 4; j++)
                    cpa16(sB1u + (cur ^ 1) * BBUFB + bFill[j],
                          WqT + (size_t)rbB[j] * KQ + kc + 64 + kbB[j]);
                CPA_COMMIT();
            }
            uint32_t cA = sAu + cur * ABUFB + aB;
            uint32_t cB = sB1u + cur * BBUFB + bB;
#pragma unroll
            for (int s = 0; s < 4; s++) {
                uint32_t a0[4], a1[4], b[2][4];
                ldsm4(a0, cA + s * 32);
                ldsm4(a1, cA + 16 * SAH * 2 + s * 32);
#pragma unroll
                for (int q = 0; q < 2; q++) ldsm4(b[q], cB + q * (16 * SBH * 2) + s * 32);
#pragma unroll
                for (int q = 0; q < 2; q++) {
                    mma16(acc[2 * q],     a0, b[q][0], b[q][1]);
                    mma16(acc[2 * q + 1], a0, b[q][2], b[q][3]);
                    mma16(acc[4 + 2 * q],     a1, b[q][0], b[q][1]);
                    mma16(acc[4 + 2 * q + 1], a1, b[q][2], b[q][3]);
                }
            }
        }
        // in-warp softmax (each warp holds full heads) -> write q fp16 to sQh
#pragma unroll
        for (int mt = 0; mt < 2; mt++)
#pragma unroll
            for (int rh = 0; rh < 2; rh++) {
                float v[8];
#pragma unroll
                for (int nt = 0; nt < 4; nt++) {
                    v[2 * nt]     = acc[mt * 4 + nt][rh * 2];
                    v[2 * nt + 1] = acc[mt * 4 + nt][rh * 2 + 1];
                }
                float m = v[0];
#pragma unroll
                for (int j = 1; j < 8; j++) m = fmaxf(m, v[j]);
                m = fmaxf(m, __shfl_xor_sync(0xffffffffu, m, 1));
                m = fmaxf(m, __shfl_xor_sync(0xffffffffu, m, 2));
                float s = 0.f;
#pragma unroll
                for (int j = 0; j < 8; j++) { v[j] = __expf(v[j] - m); s += v[j]; }
                s += __shfl_xor_sync(0xffffffffu, s, 1);
                s += __shfl_xor_sync(0xffffffffu, s, 2);
                float inv = SCALE / s;
                int r = wr1 * 32 + mt * 16 + rh * 8 + g;
#pragma unroll
                for (int nt = 0; nt < 4; nt++) {
                    int c = wc4 * 32 + nt * 8 + 2 * t;
                    *(__half2*)(sQh + r * SQH + c) =
                        __floats2half2_rn(v[2 * nt] * inv, v[2 * nt + 1] * inv);
                }
            }
        __syncthreads();
    }

    // ======= Phase 2+3: group0 k=ctx@Wk, group1 v=ctx@Wv (shared A, one pass) =======
    {
#pragma unroll
        for (int i = 0; i < 16; i++) { acc[i][0] = acc[i][1] = acc[i][2] = acc[i][3] = 0.f; }
        float4 pa[4];
#pragma unroll
        for (int j = 0; j < 4; j++)
            pa[j] = *(const float4*)(ctx + (size_t)(rowBase + raA[j]) * KC + kaA[j]);
#pragma unroll
        for (int j = 0; j < 4; j++) {
            cpa16(sB1u + bFill[j], WkT + (size_t)rbB[j] * KC + kbB[j]);
            cpa16(sB2u + bFill[j], WvT + (size_t)rbB[j] * KC + kbB[j]);
        }
        CPA_COMMIT();
        uint32_t aB = (uint32_t)(wr * 32 * SAH * 2) + aOff;
        uint32_t bB = (uint32_t)(wcg * 64 * SBH * 2) + bOff;
        uint32_t myBu = grp ? sB2u : sB1u;
#pragma unroll 1
        for (int i = 0; i < 12; i++) {
            int kc = i * 64, cur = i & 1;
            __half* dA = sAh + cur * (ABUFB / 2);
#pragma unroll
            for (int j = 0; j < 4; j++)
                *(uint2*)(dA + raA[j] * SAH + kaA[j]) = f4toh4(pa[j]);
            if (i + 1 < 12) {
#pragma unroll
                for (int j = 0; j < 4; j++)
                    pa[j] = *(const float4*)(ctx + (size_t)(rowBase + raA[j]) * KC + kc + 64 + kaA[j]);
            }
            CPA_WAIT0();
            __syncthreads();
            if (i + 1 < 12) {
#pragma unroll
                for (int j = 0; j < 4; j++) {
                    cpa16(sB1u + (cur ^ 1) * BBUFB + bFill[j],
                          WkT + (size_t)rbB[j] * KC + kc + 64 + kbB[j]);
                    cpa16(sB2u + (cur ^ 1) * BBUFB + bFill[j],
                          WvT + (size_t)rbB[j] * KC + kc + 64 + kbB[j]);
                }
                CPA_COMMIT();
            }
            uint32_t cA = sAu + cur * ABUFB + aB;
            uint32_t cB = myBu + cur * BBUFB + bB;
#pragma unroll
            for (int s = 0; s < 4; s++) {
                uint32_t a0[4], a1[4], b[4][4];
                ldsm4(a0, cA + s * 32);
                ldsm4(a1, cA + 16 * SAH * 2 + s * 32);
#pragma unroll
                for (int q = 0; q < 4; q++) ldsm4(b[q], cB + q * (16 * SBH * 2) + s * 32);
#pragma unroll
                for (int q = 0; q < 4; q++) {
                    mma16(acc[2 * q],     a0, b[q][0], b[q][1]);
                    mma16(acc[2 * q + 1], a0, b[q][2], b[q][3]);
                    mma16(acc[8 + 2 * q],     a1, b[q][0], b[q][1]);
                    mma16(acc[8 + 2 * q + 1], a1, b[q][2], b[q][3]);
                }
            }
        }
        // k-group: s[row][head] = <sigmoid(k), q> (q fp16 in sQh)
        if (grp == 0) {
            float part[2][2][2] = {};
#pragma unroll
            for (int mt = 0; mt < 2; mt++)
#pragma unroll
                for (int nt = 0; nt < 8; nt++) {
                    int hl = nt >> 2;
                    int r = wr * 32 + mt * 16 + g, c = wcg * 64 + nt * 8 + 2 * t;
#pragma unroll
                    for (int e = 0; e < 4; e++) {
                        int rr = r + (e >> 1) * 8, cc = c + (e & 1);
                        float kv = 1.f / (1.f + __expf(-acc[mt * 8 + nt][e]));
                        part[mt][e >> 1][hl] += kv * __half2float(sQh[rr * SQH + cc]);
                    }
                }
#pragma unroll
            for (int mt = 0; mt < 2; mt++)
#pragma unroll
                for (int rh = 0; rh < 2; rh++)
#pragma unroll
                    for (int hl = 0; hl < 2; hl++) {
                        float v = part[mt][rh][hl];
                        v += __shfl_xor_sync(0xffffffffu, v, 1);
                        v += __shfl_xor_sync(0xffffffffu, v, 2);
                        if (t == 0)
                            sS[(wr * 32 + mt * 16 + rh * 8 + g) * 4 + wcg * 2 + hl] = v;
                    }
        }
        __syncthreads();
        // v-group: out = s*v -> sQh (fp16, overwrites q)
        if (grp == 1) {
#pragma unroll
            for (int mt = 0; mt < 2; mt++)
#pragma unroll
                for (int nt = 0; nt < 8; nt++) {
                    int hl = nt >> 2;
                    int r = wr * 32 + mt * 16 + g, c = wcg * 64 + nt * 8 + 2 * t;
#pragma unroll
                    for (int rh = 0; rh < 2; rh++) {
                        int rr = r + rh * 8;
                        float s = sS[rr * 4 + wcg * 2 + hl];
                        __half2 h = __floats2half2_rn(s * acc[mt * 8 + nt][rh * 2],
                                                      s * acc[mt * 8 + nt][rh * 2 + 1]);
                        *(__half2*)(sQh + rr * SQH + c) = h;
                    }
                }
        }
        __syncthreads();
    }

    // ===== Phase 4: y = out @ Wo + bo; two nc blocks concurrently (one per group) =====
    {
        int gt = tid & 127;
        int rn[8], rk[8];
        uint32_t bF4[8];
#pragma unroll
        for (int j = 0; j < 8; j++) {
            int idx = gt + j * 128;
            rn[j] = idx >> 3; rk[j] = (idx & 7) << 3;
            bF4[j] = (uint32_t)((rn[j] * SBH + rk[j]) * 2);
        }
        uint32_t sBgu = grp ? sB2u : sB1u;
#pragma unroll
        for (int j = 0; j < 8; j++)
            cpa16(sBgu + bF4[j], WoT + (size_t)(grp * 128 + rn[j]) * HID + rk[j]);
        CPA_COMMIT();
        uint32_t bB = (uint32_t)(wcg * 64 * SBH * 2) + bOff;
        uint32_t qB = (uint32_t)(wr * 32 * SQH * 2) + qOff;
#pragma unroll 1
        for (int i = 0; i < 4; i++) {
            int kc = (i & 1) * 64, cur = i & 1;
            int nc = (i >> 1) * 2 + grp;
            if ((i & 1) == 0) {
#pragma unroll
                for (int q = 0; q < 16; q++) { acc[q][0] = acc[q][1] = acc[q][2] = acc[q][3] = 0.f; }
            }
            CPA_WAIT0();
            __syncthreads();
            if (i + 1 < 4) {
                int n = i + 1, nk = (n & 1) * 64, nnc = (n >> 1) * 2 + grp;
#pragma unroll
                for (int j = 0; j < 8; j++)
                    cpa16(sBgu + (cur ^ 1) * BBUFB + bF4[j],
                          WoT + (size_t)(nnc * 128 + rn[j]) * HID + nk + rk[j]);
                CPA_COMMIT();
            }
            uint32_t cB = sBgu + cur * BBUFB + bB;
            uint32_t cQ = sQhu + qB + kc * 2;
#pragma unroll
            for (int s = 0; s < 4; s++) {
                uint32_t a0[4], a1[4], b[4][4];
                ldsm4(a0, cQ + s * 32);
                ldsm4(a1, cQ + 16 * SQH * 2 + s * 32);
#pragma unroll
                for (int q = 0; q < 4; q++) ldsm4(b[q], cB + q * (16 * SBH * 2) + s * 32);
#pragma unroll
                for (int q = 0; q < 4; q++) {
                    mma16(acc[2 * q],     a0, b[q][0], b[q][1]);
                    mma16(acc[2 * q + 1], a0, b[q][2], b[q][3]);
                    mma16(acc[8 + 2 * q],     a1, b[q][0], b[q][1]);
                    mma16(acc[8 + 2 * q + 1], a1, b[q][2], b[q][3]);
                }
            }
            if ((i & 1) == 1) {  // finish nc block: write y, accumulate sum-squares
                float rss[2][2] = {};
#pragma unroll
                for (int mt = 0; mt < 2; mt++)
#pragma unroll
                    for (int nt = 0; nt < 8; nt++) {
                        int r = wr * 32 + mt * 16 + g;
                        int c = nc * 128 + wcg * 64 + nt * 8 + 2 * t;
#pragma unroll
                        for (int e = 0; e < 4; e++) {
                            int rr = r + (e >> 1) * 8, cc = c + (e & 1);
                            float y = acc[mt * 8 + nt][e] + __ldg(bo + cc);
                            out[(size_t)(rowBase + rr) * DIMO + cc] = y;
                            rss[mt][e >> 1] += y * y;
                        }
                    }
#pragma unroll
                for (int mt = 0; mt < 2; mt++)
#pragma unroll
                    for (int rh = 0; rh < 2; rh++) {
                        float v = rss[mt][rh];
                        v += __shfl_xor_sync(0xffffffffu, v, 1);
                        v += __shfl_xor_sync(0xffffffffu, v, 2);
                        if (t == 0) atomicAdd(&sSS[wr * 32 + mt * 16 + rh * 8 + g], v);
                    }
            }
        }
    }
    __syncthreads();

    // ---- Phase 5: RMS-normalize in place (rows are L2-hot) ----
#pragma unroll 1
    for (int i4 = tid; i4 < ROWS * DIMO / 4; i4 += NT) {
        int r = i4 >> 7, c4 = (i4 & 127) << 2;
        float* p = out + (size_t)(rowBase + r) * DIMO + c4;
        float4 y = *(float4*)p;
        float sc = rsqrtf(fmaxf(sSS[r], 1e-24f)) * SQRTD;
        float4 gv = *(const float4*)(gg + c4);
        y.x *= sc * gv.x; y.y *= sc * gv.y; y.z *= sc * gv.z; y.w *= sc * gv.w;
        *(float4*)p = y;
    }
}

extern "C" void kernel_launch(void* const* d_in, const int* in_sizes, int n_in,
                              void* d_out, int out_size) {
    const float* x   = (const float*)d_in[0];
    const float* ctx = (const float*)d_in[1];
    const float* Wq  = (const float*)d_in[2];
    const float* Wk  = (const float*)d_in[3];
    const float* Wv  = (const float*)d_in[4];
    const float* Wo  = (const float*)d_in[5];
    const float* bo  = (const float*)d_in[6];
    const float* gg  = (const float*)d_in[7];
    wtrans<<<320, dim3(32, 8)>>>(Wq, Wk, Wv, Wo);
    cudaFuncSetAttribute(lca_kernel, cudaFuncAttributeMaxDynamicSharedMemorySize, SMEM_BYTES);
    lca_kernel<<<1024, NT, SMEM_BYTES>>>(x, ctx, bo, gg, (float*)d_out);
}